// round 4
// baseline (speedup 1.0000x reference)
#include <cuda_runtime.h>
#include <cstdint>

// Problem constants
#define N_SEL 256
#define PTS   2048
#define D_IN  256
#define D_OUT 256
#define TILES 8

// Tiling
#define TILE_M 128
#define TILE_N 128
#define TILE_K 32
#define NTHREADS 256

#define A_STRIDE (TILE_K + 4)            // 36 floats (pad: conflict-free LDS, keeps 16B align)
#define B_STRIDE (TILE_N + 4)            // 132 floats
#define A_FLOATS (TILE_M * A_STRIDE)     // 4608
#define B_FLOATS (TILE_K * B_STRIDE)     // 4224
#define STAGE_FLOATS (A_FLOATS + B_FLOATS)   // 8832
#define SMEM_BYTES (2 * STAGE_FLOATS * 4)    // 70656

__device__ int g_t;
__device__ int g_idx[N_SEL];

// Resolve t and indices (handles both int32 and int64 index dtype).
// If indices are int64, values are < 256, so every odd 32-bit word in the
// first 256 words is the zero high-half. If int32, 128 random indices all
// being zero has probability ~(1/256)^128 ~ 0.
__global__ void setup_kernel(const int* __restrict__ idx_words,
                             const int* __restrict__ t_words, int has_t) {
    __shared__ int is64;
    if (threadIdx.x == 0) {
        g_t = has_t ? t_words[0] : 3;   // int32/int64 little-endian: first word is the value
        int oro = 0;
        for (int i = 1; i < 256; i += 2) oro |= idx_words[i];
        is64 = (oro == 0) ? 1 : 0;
    }
    __syncthreads();
    int i = threadIdx.x;
    if (i < N_SEL) g_idx[i] = is64 ? idx_words[2 * i] : idx_words[i];
}

__device__ __forceinline__ uint32_t f2tf32(float x) {
    uint32_t u;
    asm("cvt.rna.tf32.f32 %0, %1;" : "=r"(u) : "f"(x));
    return u;
}

__device__ __forceinline__ void cp16(uint32_t saddr, const void* g) {
    asm volatile("cp.async.cg.shared.global [%0], [%1], 16;\n"
                 :: "r"(saddr), "l"(g));
}

__device__ __forceinline__ void cp_commit() {
    asm volatile("cp.async.commit_group;\n");
}
__device__ __forceinline__ void cp_wait0() {
    asm volatile("cp.async.wait_group 0;\n");
}

__global__ void __launch_bounds__(NTHREADS, 2)
gemm_tf32_kernel(const float* __restrict__ X, const float* __restrict__ W,
                 const float* __restrict__ Bs, float* __restrict__ O)
{
    extern __shared__ float smem[];
    const int tid  = threadIdx.x;
    const int lane = tid & 31;
    const int warp = tid >> 5;
    const int warp_m = warp & 1;       // 0..1  -> 64-row warp tile
    const int warp_n = warp >> 1;      // 0..3  -> 32-col warp tile

    const int bidx  = blockIdx.x;
    const int batch = bidx >> 5;       // 32 tiles per batch
    const int tile  = bidx & 31;
    const int m0 = (tile >> 1) * TILE_M;
    const int n0 = (tile & 1) * TILE_N;

    const int ch = g_idx[batch];
    const int t  = g_t;
    const float* Ag = X + ((size_t)batch * PTS + m0) * D_IN;
    const float* Wg = W + ((size_t)ch * TILES + t) * (size_t)(D_IN * D_OUT) + n0;
    const float* Bg = Bs + ((size_t)ch * TILES + t) * D_OUT + n0;

    float* sAp[2] = { smem,                smem + STAGE_FLOATS };
    float* sBp[2] = { smem + A_FLOATS,     smem + STAGE_FLOATS + A_FLOATS };
    uint32_t sAa[2], sBa[2];
    sAa[0] = (uint32_t)__cvta_generic_to_shared(sAp[0]);
    sAa[1] = (uint32_t)__cvta_generic_to_shared(sAp[1]);
    sBa[0] = (uint32_t)__cvta_generic_to_shared(sBp[0]);
    sBa[1] = (uint32_t)__cvta_generic_to_shared(sBp[1]);

    float acc[4][4][4];
#pragma unroll
    for (int mi = 0; mi < 4; mi++)
#pragma unroll
        for (int ni = 0; ni < 4; ni++)
#pragma unroll
            for (int r = 0; r < 4; r++) acc[mi][ni][r] = 0.0f;

    // ---- async load of one K-chunk into stage s ----
    auto load_chunk = [&](int s, int kc) {
#pragma unroll
        for (int it = 0; it < 4; it++) {            // A: 128 rows x 32 floats
            int idx = tid + it * NTHREADS;          // 1024 x 16B
            int r = idx >> 3, c = idx & 7;
            cp16(sAa[s] + (uint32_t)(r * A_STRIDE + c * 4) * 4,
                 Ag + (size_t)r * D_IN + kc * TILE_K + c * 4);
        }
#pragma unroll
        for (int it = 0; it < 4; it++) {            // B: 32 rows x 128 floats
            int idx = tid + it * NTHREADS;
            int r = idx >> 5, c = idx & 31;
            cp16(sBa[s] + (uint32_t)(r * B_STRIDE + c * 4) * 4,
                 Wg + (size_t)(kc * TILE_K + r) * D_OUT + c * 4);
        }
        cp_commit();
    };

    const int NCHUNK = D_IN / TILE_K;   // 8
    load_chunk(0, 0);

    for (int kc = 0; kc < NCHUNK; kc++) {
        cp_wait0();
        __syncthreads();
        if (kc + 1 < NCHUNK) load_chunk((kc + 1) & 1, kc + 1);

        const float* sA = sAp[kc & 1];
        const float* sB = sBp[kc & 1];

#pragma unroll
        for (int ks = 0; ks < 4; ks++) {
            const int k = ks * 8;
            uint32_t a[4][4];
#pragma unroll
            for (int mi = 0; mi < 4; mi++) {
                const int r = warp_m * 64 + mi * 16 + (lane >> 2);
                const float* base = sA + r * A_STRIDE + k + (lane & 3);
                a[mi][0] = f2tf32(base[0]);
                a[mi][1] = f2tf32(base[8 * A_STRIDE]);
                a[mi][2] = f2tf32(base[4]);
                a[mi][3] = f2tf32(base[8 * A_STRIDE + 4]);
            }
            uint32_t b[4][2];
#pragma unroll
            for (int ni = 0; ni < 4; ni++) {
                const int c = warp_n * 32 + ni * 8 + (lane >> 2);
                const float* base = sB + (k + (lane & 3)) * B_STRIDE + c;
                b[ni][0] = f2tf32(base[0]);
                b[ni][1] = f2tf32(base[4 * B_STRIDE]);
            }
#pragma unroll
            for (int mi = 0; mi < 4; mi++)
#pragma unroll
                for (int ni = 0; ni < 4; ni++) {
                    asm volatile(
                        "mma.sync.aligned.m16n8k8.row.col.f32.tf32.tf32.f32 "
                        "{%0,%1,%2,%3}, {%4,%5,%6,%7}, {%8,%9}, {%0,%1,%2,%3};\n"
                        : "+f"(acc[mi][ni][0]), "+f"(acc[mi][ni][1]),
                          "+f"(acc[mi][ni][2]), "+f"(acc[mi][ni][3])
                        : "r"(a[mi][0]), "r"(a[mi][1]), "r"(a[mi][2]), "r"(a[mi][3]),
                          "r"(b[ni][0]), "r"(b[ni][1]));
                }
        }
        __syncthreads();
    }

    // ---- epilogue: + bias, write fp32 ----
    float2 bv[4];
#pragma unroll
    for (int ni = 0; ni < 4; ni++) {
        const int col = warp_n * 32 + ni * 8 + (lane & 3) * 2;
        bv[ni] = *(const float2*)(Bg + col);
    }
#pragma unroll
    for (int mi = 0; mi < 4; mi++) {
        const int r0 = m0 + warp_m * 64 + mi * 16 + (lane >> 2);
        float* o0 = O + ((size_t)batch * PTS + r0) * D_OUT + n0;
        float* o1 = o0 + (size_t)8 * D_OUT;
#pragma unroll
        for (int ni = 0; ni < 4; ni++) {
            const int col = warp_n * 32 + ni * 8 + (lane & 3) * 2;
            float2 v0 = { acc[mi][ni][0] + bv[ni].x, acc[mi][ni][1] + bv[ni].y };
            float2 v1 = { acc[mi][ni][2] + bv[ni].x, acc[mi][ni][3] + bv[ni].y };
            *(float2*)(o0 + col) = v0;
            *(float2*)(o1 + col) = v1;
        }
    }
}

extern "C" void kernel_launch(void* const* d_in, const int* in_sizes, int n_in,
                              void* d_out, int out_size) {
    const float* x   = (const float*)d_in[0];
    const float* w   = (const float*)d_in[1];
    const float* b   = (const float*)d_in[2];
    const int*   idx = (const int*)d_in[3];
    const int*   tp  = (n_in > 4) ? (const int*)d_in[4] : nullptr;
    float*       out = (float*)d_out;

    (void)in_sizes; (void)out_size;

    cudaFuncSetAttribute(gemm_tf32_kernel,
                         cudaFuncAttributeMaxDynamicSharedMemorySize, SMEM_BYTES);

    setup_kernel<<<1, 256>>>(idx, tp, (n_in > 4) ? 1 : 0);

    const int grid = N_SEL * (PTS / TILE_M) * (D_OUT / TILE_N);  // 8192
    gemm_tf32_kernel<<<grid, NTHREADS, SMEM_BYTES>>>(x, w, b, out);
}